// round 14
// baseline (speedup 1.0000x reference)
#include <cuda_runtime.h>
#include <cuda_bf16.h>
#include <cstdint>

#define BATCH 16
#define CIN1  80
#define CMID  256
#define TLEN  4096
#define EMB   128
#define DSTR  12
#define TP    341
#define VQD   16
#define NQ    8
#define NCODE 256

#define EA_SIZE (BATCH*EMB*TP)     // 698368
#define POSN    (BATCH*TP)         // 5456

typedef unsigned long long u64;
typedef __nv_bfloat162 bf2;

// ---------------- helpers ----------------
__device__ __forceinline__ u64 ffma2(u64 a, u64 b, u64 c) {
    u64 d;
    asm("fma.rn.f32x2 %0, %1, %2, %3;" : "=l"(d) : "l"(a), "l"(b), "l"(c));
    return d;
}
__device__ __forceinline__ float2 u2f2(u64 u) {
    float2 f;
    asm("mov.b64 {%0, %1}, %2;" : "=f"(f.x), "=f"(f.y) : "l"(u));
    return f;
}
// 3-way bf16 split: x == h + m + l exactly (8+8+8 bits cover fp32's 24-bit mantissa)
__device__ __forceinline__ void split3(float x, __nv_bfloat16& h, __nv_bfloat16& m,
                                       __nv_bfloat16& l) {
    h = __float2bfloat16_rn(x);
    float r1 = x - __bfloat162float(h);
    m = __float2bfloat16_rn(r1);
    float r2 = r1 - __bfloat162float(m);
    l = __float2bfloat16_rn(r2);
}
// D += A(16x16) * B(16x8), bf16 in, f32 accum
__device__ __forceinline__ void mma_bf16(float* c, unsigned a0, unsigned a1,
                                         unsigned a2, unsigned a3,
                                         unsigned b0, unsigned b1) {
    asm("mma.sync.aligned.m16n8k16.row.col.f32.bf16.bf16.f32 "
        "{%0,%1,%2,%3}, {%4,%5,%6,%7}, {%8,%9}, {%0,%1,%2,%3};"
        : "+f"(c[0]), "+f"(c[1]), "+f"(c[2]), "+f"(c[3])
        : "r"(a0), "r"(a1), "r"(a2), "r"(a3), "r"(b0), "r"(b1));
}

// -------- scratch (device globals; no runtime allocation) --------
__device__ float g_x1[(size_t)BATCH*CMID*TLEN];
__device__ float g_x2[(size_t)BATCH*CMID*TLEN];
__device__ float g_z [(size_t)POSN*VQD];
// pre-split activations: [b][c2][t], bf2 = {x[2c2], x[2c2+1]}
#define MS_WORDS  ((size_t)BATCH*(CIN1/2)*TLEN)
#define X1S_WORDS ((size_t)BATCH*(CMID/2)*TLEN)
__device__ bf2 g_msh[MS_WORDS],  g_msm[MS_WORDS],  g_msl[MS_WORDS];
__device__ bf2 g_x1h[X1S_WORDS], g_x1m[X1S_WORDS], g_x1l[X1S_WORDS];
// pre-split weights: [chunk][kw*8+ci2][co], bf2 = {w ci even, ci odd}
#define WT2_WORDS ((size_t)(CMID/16)*5*8*CMID)
#define WT1_WORDS ((size_t)(CIN1/16)*5*8*CMID)
__device__ bf2 g_wt2h[WT2_WORDS], g_wt2m[WT2_WORDS], g_wt2l[WT2_WORDS];
__device__ bf2 g_wt1h[WT1_WORDS], g_wt1m[WT1_WORDS], g_wt1l[WT1_WORDS];

// ============================================================================
// Activation split: X [B][C][T] fp32 -> 3 bf2 arrays [B][C/2][T]
// ============================================================================
__global__ void xsplit_kernel(const float* __restrict__ X,
                              bf2* __restrict__ oh, bf2* __restrict__ om,
                              bf2* __restrict__ ol, int C)
{
    size_t idx = (size_t)blockIdx.x * 256 + threadIdx.x;
    int C2 = C >> 1;
    size_t per_b = (size_t)C2 * TLEN;
    size_t total = (size_t)BATCH * per_b;
    if (idx >= total) return;
    int b  = (int)(idx / per_b);
    size_t c2t = idx - (size_t)b * per_b;
    int c2 = (int)(c2t / TLEN);
    int t  = (int)(c2t - (size_t)c2 * TLEN);
    const float* src = X + ((size_t)b*C + 2*c2)*TLEN + t;
    float x0 = src[0], x1 = src[TLEN];
    __nv_bfloat16 h0,m0,l0,h1,m1,l1;
    split3(x0, h0, m0, l0);
    split3(x1, h1, m1, l1);
    oh[idx] = __halves2bfloat162(h0, h1);
    om[idx] = __halves2bfloat162(m0, m1);
    ol[idx] = __halves2bfloat162(l0, l1);
}

// ============================================================================
// Weight transform: w (256, Cin, 5) -> [chunk][kw][ci2][co] {ci even, ci odd}
// ============================================================================
__global__ void wtrans_kernel(const float* __restrict__ w,
                              bf2* __restrict__ th, bf2* __restrict__ tm,
                              bf2* __restrict__ tl, int Cin)
{
    int idx = blockIdx.x * 256 + threadIdx.x;
    int total = (Cin/16) * 5 * 8 * 256;
    if (idx >= total) return;
    int co   = idx & 255;
    int rest = idx >> 8;
    int ci2  = rest & 7;
    int kw   = (rest >> 3) % 5;
    int chunk = rest / 40;
    int ci0 = chunk*16 + 2*ci2;
    float w0 = w[(size_t)co*Cin*5 + (size_t)ci0*5 + kw];
    float w1 = w[(size_t)co*Cin*5 + (size_t)(ci0+1)*5 + kw];
    __nv_bfloat16 h0,m0,l0,h1,m1,l1;
    split3(w0, h0, m0, l0);
    split3(w1, h1, m1, l1);
    th[idx] = __halves2bfloat162(h0, h1);
    tm[idx] = __halves2bfloat162(m0, m1);
    tl[idx] = __halves2bfloat162(l0, l1);
}

// ============================================================================
// Implicit-GEMM conv (k=5, pad=2, Cout=256) + BN + ReLU, bf16x6 split.
// 6 mmas per k16 (mm, hl, lh, hm, mh, hh; dropped ml/lm ~2^-26). Short-chain
// temp-C + RN flush kills the tensor-core RZ-chain bias (proven in R11).
// block 256 (8 warps), tile M=64 co x N=64 t; warp m16 x n32.
// ============================================================================
#define XSS 72
#define WSS 72

__global__ __launch_bounds__(256, 2)
void convmma_kernel(const bf2* __restrict__ xh_, const bf2* __restrict__ xm_,
                    const bf2* __restrict__ xl_,
                    const bf2* __restrict__ wth, const bf2* __restrict__ wtm,
                    const bf2* __restrict__ wtl,
                    float* __restrict__ Y, int Cin,
                    const float* __restrict__ cb_, const float* __restrict__ g_,
                    const float* __restrict__ be_, const float* __restrict__ m_,
                    const float* __restrict__ v_)
{
    __shared__ bf2 xsh[8*XSS], xsm[8*XSS], xsl[8*XSS];
    __shared__ bf2 wsh[40*WSS], wsm[40*WSS], wsl[40*WSS];

    const int t0   = blockIdx.x * 64;
    const int co0  = blockIdx.y * 64;
    const int b    = blockIdx.z;
    const int tid  = threadIdx.x;
    const int lane = tid & 31;
    const int wid  = tid >> 5;
    const int wm   = wid & 3;
    const int wn   = wid >> 2;
    const int qr   = lane >> 2;
    const int qc   = lane & 3;

    const int C2 = Cin >> 1;

    float cm[4][4];
#pragma unroll
    for (int j = 0; j < 4; j++)
#pragma unroll
        for (int i = 0; i < 4; i++) cm[j][i] = 0.f;

    const unsigned* uxsh = (const unsigned*)xsh;
    const unsigned* uxsm = (const unsigned*)xsm;
    const unsigned* uxsl = (const unsigned*)xsl;
    const unsigned* uwsh = (const unsigned*)wsh;
    const unsigned* uwsm = (const unsigned*)wsm;
    const unsigned* uwsl = (const unsigned*)wsl;

    const bf2 hz = __float2bfloat162_rn(0.f);

    const int nchunk = Cin >> 4;
    for (int chunk = 0; chunk < nchunk; chunk++) {
        __syncthreads();
        // stage x: 8 c2 rows x 68 t, 3 levels, direct copy from pre-split gmem
#pragma unroll
        for (int lev = 0; lev < 3; lev++) {
            const bf2* Xs = (lev == 0 ? xh_ : (lev == 1 ? xm_ : xl_))
                            + ((size_t)b*C2 + chunk*8)*TLEN;
            bf2* dst = (lev == 0 ? xsh : (lev == 1 ? xsm : xsl));
            for (int i = tid; i < 8*68; i += 256) {
                int r = i / 68, j = i - r*68;
                int t = t0 - 2 + j;
                bf2 v = hz;
                if (t >= 0 && t < TLEN) v = Xs[(size_t)r*TLEN + t];
                dst[r*XSS + j] = v;
            }
        }
        // stage w: 40 rows x 64 co, 3 levels, uint4 vectorized
        {
            const size_t srcbase = (size_t)chunk * 40 * 256 + co0;
            for (int i = tid; i < 40*16*3; i += 256) {
                int lev = i / 640;
                int rem = i - lev*640;
                int r = rem >> 4, q = (rem & 15) << 2;
                const bf2* src = (lev == 0 ? wth : (lev == 1 ? wtm : wtl))
                                 + srcbase + (size_t)r*256 + q;
                bf2* dst = (lev == 0 ? wsh : (lev == 1 ? wsm : wsl)) + r*WSS + q;
                *(uint4*)dst = *(const uint4*)src;
            }
        }
        __syncthreads();

#pragma unroll
        for (int kw = 0; kw < 5; kw++) {
            const int ra = (kw*8 + qc)*WSS + wm*16 + qr;
            const int rb = (kw*8 + qc + 4)*WSS + wm*16 + qr;
            unsigned Ah0 = uwsh[ra], Ah1 = uwsh[ra+8], Ah2 = uwsh[rb], Ah3 = uwsh[rb+8];
            unsigned Am0 = uwsm[ra], Am1 = uwsm[ra+8], Am2 = uwsm[rb], Am3 = uwsm[rb+8];
            unsigned Al0 = uwsl[ra], Al1 = uwsl[ra+8], Al2 = uwsl[rb], Al3 = uwsl[rb+8];
#pragma unroll
            for (int j = 0; j < 4; j++) {
                const int toff = wn*32 + j*8 + qr + kw;
                const int x0i = qc*XSS + toff;
                const int x1i = (qc+4)*XSS + toff;
                unsigned Bh0 = uxsh[x0i], Bh1 = uxsh[x1i];
                unsigned Bm0 = uxsm[x0i], Bm1 = uxsm[x1i];
                unsigned Bl0 = uxsl[x0i], Bl1 = uxsl[x1i];
                // 6 terms ascending magnitude into zeroed temp; RN flush
                float ct[4] = {0.f, 0.f, 0.f, 0.f};
                mma_bf16(ct, Am0,Am1,Am2,Am3, Bm0,Bm1);   // m*m ~2^-18
                mma_bf16(ct, Ah0,Ah1,Ah2,Ah3, Bl0,Bl1);   // h*l ~2^-17
                mma_bf16(ct, Al0,Al1,Al2,Al3, Bh0,Bh1);   // l*h ~2^-17
                mma_bf16(ct, Am0,Am1,Am2,Am3, Bh0,Bh1);   // m*h ~2^-9
                mma_bf16(ct, Ah0,Ah1,Ah2,Ah3, Bm0,Bm1);   // h*m ~2^-9
                mma_bf16(ct, Ah0,Ah1,Ah2,Ah3, Bh0,Bh1);   // h*h ~1
#pragma unroll
                for (int i = 0; i < 4; i++) cm[j][i] += ct[i];
            }
        }
    }

    const int r0 = co0 + wm*16 + qr;
    const int r1 = r0 + 8;
    float s0 = g_[r0] * rsqrtf(v_[r0] + 1e-5f);
    float s1 = g_[r1] * rsqrtf(v_[r1] + 1e-5f);
    float bb0 = (cb_[r0] - m_[r0]) * s0 + be_[r0];
    float bb1 = (cb_[r1] - m_[r1]) * s1 + be_[r1];
    float* Y0 = Y + (size_t)b*CMID*TLEN + (size_t)r0*TLEN;
    float* Y1 = Y + (size_t)b*CMID*TLEN + (size_t)r1*TLEN;
#pragma unroll
    for (int j = 0; j < 4; j++) {
        int cn = t0 + wn*32 + j*8 + 2*qc;
        float y00 = fmaf(cm[j][0], s0, bb0); y00 = y00 > 0.f ? y00 : 0.f;
        float y01 = fmaf(cm[j][1], s0, bb0); y01 = y01 > 0.f ? y01 : 0.f;
        float y10 = fmaf(cm[j][2], s1, bb1); y10 = y10 > 0.f ? y10 : 0.f;
        float y11 = fmaf(cm[j][3], s1, bb1); y11 = y11 > 0.f ? y11 : 0.f;
        *(float2*)(Y0 + cn) = make_float2(y00, y01);
        *(float2*)(Y1 + cn) = make_float2(y10, y11);
    }
}

// ============================================================================
// Kernel 3: downsample conv (256->128, k=24, stride=12, pad=6). exact fp32.
// ============================================================================
#define DC 8
#define D_SMEM (DC*300*8 + DC*24*64*4)

__global__ __launch_bounds__(256, 3)
void down_kernel(const float* __restrict__ wd, const float* __restrict__ bd,
                 float* __restrict__ out)
{
    extern __shared__ float smd[];
    float2* xsd = (float2*)smd;
    float*  ws  = smd + DC*300*2;

    const int tp0 = blockIdx.x * 24;
    const int co0 = blockIdx.y * 64;
    const int b   = blockIdx.z;
    const int tid = threadIdx.x;
    const int cp  = tid & 31;
    const int tg  = tid >> 5;

    const float* xb = g_x2 + (size_t)b*CMID*TLEN;
    const int base = tp0*DSTR - 6;

    u64 acc[3] = {0ull, 0ull, 0ull};

    for (int c0 = 0; c0 < CMID; c0 += DC) {
        __syncthreads();
        for (int i = tid; i < DC*300; i += 256) {
            int ci = i / 300, j = i % 300;
            int t = base + j;
            float v = (t >= 0 && t < TLEN) ? xb[(size_t)(c0+ci)*TLEN + t] : 0.f;
            xsd[i] = make_float2(v, v);
        }
        for (int i = tid; i < DC*24*64; i += 256) {
            int co = i & 63, r = i >> 6;
            ws[i] = wd[(size_t)(co0+co)*(CMID*24) + c0*24 + r];
        }
        __syncthreads();

#pragma unroll 1
        for (int ci = 0; ci < DC; ci++) {
            const u64* xrow = (const u64*)(xsd + ci*300 + tg*36);
            const float* wrow = ws + ci*24*64 + 2*cp;
#pragma unroll 4
            for (int k = 0; k < 24; k++) {
                u64 w = *(const u64*)(wrow + k*64);
#pragma unroll
                for (int tt = 0; tt < 3; tt++)
                    acc[tt] = ffma2(w, xrow[tt*12 + k], acc[tt]);
            }
        }
    }

    const int co = co0 + 2*cp;
    const float b0 = bd[co], b1v = bd[co+1];
#pragma unroll
    for (int tt = 0; tt < 3; tt++) {
        int tp = tp0 + tg*3 + tt;
        if (tp < TP) {
            float2 v = u2f2(acc[tt]);
            out[(size_t)b*EMB*TP + (size_t)co*TP + tp]     = v.x + b0;
            out[(size_t)b*EMB*TP + (size_t)(co+1)*TP + tp] = v.y + b1v;
        }
    }
}

// ============================================================================
// Kernel 4: 1x1 projection e_a(128) -> z(16).
// ============================================================================
__global__ __launch_bounds__(256)
void proj_kernel(const float* __restrict__ out,
                 const float* __restrict__ wp, const float* __restrict__ bp)
{
    __shared__ float xs[EMB*64];
    __shared__ float wps[VQD*EMB];

    const int tp0 = blockIdx.x * 64;
    const int b   = blockIdx.y;
    const int tid = threadIdx.x;
    const int tp_l = tid & 63;
    const int dbase = tid >> 6;

    for (int i = tid; i < EMB*64; i += 256) {
        int e = i >> 6, tl = i & 63;
        int tp = tp0 + tl;
        xs[i] = (tp < TP) ? out[(size_t)b*EMB*TP + (size_t)e*TP + tp] : 0.f;
    }
    for (int i = tid; i < VQD*EMB; i += 256) wps[i] = wp[i];
    __syncthreads();

    float acc[4] = {0.f, 0.f, 0.f, 0.f};
    for (int e = 0; e < EMB; e++) {
        float xv = xs[e*64 + tp_l];
#pragma unroll
        for (int dd = 0; dd < 4; dd++)
            acc[dd] = fmaf(wps[(dd*4 + dbase)*EMB + e], xv, acc[dd]);
    }

    int tp = tp0 + tp_l;
    if (tp < TP) {
#pragma unroll
        for (int dd = 0; dd < 4; dd++) {
            int d = dd*4 + dbase;
            g_z[((size_t)b*TP + tp)*VQD + d] = acc[dd] + bp[d];
        }
    }
}

// ============================================================================
// Kernel 5: residual VQ, 8 stages.
// ============================================================================
__global__ __launch_bounds__(256)
void rvq_kernel(const float* __restrict__ codebooks, float* __restrict__ out)
{
    __shared__ float cbs[NCODE * VQD];
    __shared__ float cc[NCODE];

    const int tid = threadIdx.x;
    const int pos = blockIdx.x * 256 + tid;
    const bool valid = pos < POSN;

    float r[VQD];
    if (valid) {
#pragma unroll
        for (int d = 0; d < VQD; d++) r[d] = g_z[(size_t)pos*VQD + d];
    }

    for (int q = 0; q < NQ; q++) {
        __syncthreads();
        for (int i = tid; i < NCODE*VQD; i += 256)
            cbs[i] = codebooks[(size_t)q*NCODE*VQD + i];
        __syncthreads();
        {
            float s = 0.f;
#pragma unroll
            for (int d = 0; d < VQD; d++) {
                float c = cbs[tid*VQD + d];
                s = fmaf(c, c, s);
            }
            cc[tid] = s;
        }
        __syncthreads();

        if (valid) {
            int best = 0;
            float bestd = 3.4e38f;
            for (int code = 0; code < NCODE; code++) {
                float dot = 0.f;
#pragma unroll
                for (int d = 0; d < VQD; d++)
                    dot = fmaf(r[d], cbs[code*VQD + d], dot);
                float sc = cc[code] - 2.f*dot;
                if (sc < bestd) { bestd = sc; best = code; }
            }
            out[EA_SIZE + (size_t)q*POSN + pos] = (float)best;
#pragma unroll
            for (int d = 0; d < VQD; d++) r[d] -= cbs[best*VQD + d];
        }
    }
}

// ============================================================================
extern "C" void kernel_launch(void* const* d_in, const int* in_sizes, int n_in,
                              void* d_out, int out_size)
{
    const float* mel = (const float*)d_in[0];
    const float* w1  = (const float*)d_in[1];
    const float* b1  = (const float*)d_in[2];
    const float* g1  = (const float*)d_in[3];
    const float* be1 = (const float*)d_in[4];
    const float* m1  = (const float*)d_in[5];
    const float* v1  = (const float*)d_in[6];
    const float* w2  = (const float*)d_in[7];
    const float* b2  = (const float*)d_in[8];
    const float* g2  = (const float*)d_in[9];
    const float* be2 = (const float*)d_in[10];
    const float* m2  = (const float*)d_in[11];
    const float* v2  = (const float*)d_in[12];
    const float* wd  = (const float*)d_in[13];
    const float* bd  = (const float*)d_in[14];
    const float* wp  = (const float*)d_in[15];
    const float* bp  = (const float*)d_in[16];
    const float* cb  = (const float*)d_in[17];
    float* out = (float*)d_out;

    bf2 *w2h, *w2m, *w2l, *w1h, *w1m, *w1l;
    cudaGetSymbolAddress((void**)&w2h, g_wt2h);
    cudaGetSymbolAddress((void**)&w2m, g_wt2m);
    cudaGetSymbolAddress((void**)&w2l, g_wt2l);
    cudaGetSymbolAddress((void**)&w1h, g_wt1h);
    cudaGetSymbolAddress((void**)&w1m, g_wt1m);
    cudaGetSymbolAddress((void**)&w1l, g_wt1l);
    bf2 *msh, *msm, *msl, *x1h, *x1m, *x1l;
    cudaGetSymbolAddress((void**)&msh, g_msh);
    cudaGetSymbolAddress((void**)&msm, g_msm);
    cudaGetSymbolAddress((void**)&msl, g_msl);
    cudaGetSymbolAddress((void**)&x1h, g_x1h);
    cudaGetSymbolAddress((void**)&x1m, g_x1m);
    cudaGetSymbolAddress((void**)&x1l, g_x1l);
    float *x1p, *x2p;
    cudaGetSymbolAddress((void**)&x1p, g_x1);
    cudaGetSymbolAddress((void**)&x2p, g_x2);

    cudaFuncSetAttribute(down_kernel, cudaFuncAttributeMaxDynamicSharedMemorySize, D_SMEM);

    wtrans_kernel<<<((CMID/16)*5*8*256 + 255)/256, 256>>>(w2, w2h, w2m, w2l, CMID);
    wtrans_kernel<<<((CIN1/16)*5*8*256 + 255)/256, 256>>>(w1, w1h, w1m, w1l, CIN1);
    xsplit_kernel<<<(int)((MS_WORDS + 255)/256), 256>>>(mel, msh, msm, msl, CIN1);
    convmma_kernel<<<dim3(TLEN/64, CMID/64, BATCH), 256>>>(
        msh, msm, msl, w1h, w1m, w1l, x1p, CIN1, b1, g1, be1, m1, v1);
    xsplit_kernel<<<(int)((X1S_WORDS + 255)/256), 256>>>(x1p, x1h, x1m, x1l, CMID);
    convmma_kernel<<<dim3(TLEN/64, CMID/64, BATCH), 256>>>(
        x1h, x1m, x1l, w2h, w2m, w2l, x2p, CMID, b2, g2, be2, m2, v2);
    down_kernel<<<dim3((TP + 23)/24, EMB/64, BATCH), 256, D_SMEM>>>(wd, bd, out);
    proj_kernel<<<dim3((TP + 63)/64, BATCH), 256>>>(out, wp, bp);
    rvq_kernel<<<(POSN + 255)/256, 256>>>(cb, out);
}

// round 15
// speedup vs baseline: 1.1557x; 1.1557x over previous
#include <cuda_runtime.h>
#include <cuda_bf16.h>
#include <cstdint>

#define BATCH 16
#define CIN1  80
#define CMID  256
#define TLEN  4096
#define EMB   128
#define DSTR  12
#define TP    341
#define VQD   16
#define NQ    8
#define NCODE 256

#define EA_SIZE (BATCH*EMB*TP)     // 698368
#define POSN    (BATCH*TP)         // 5456

typedef unsigned long long u64;
typedef __nv_bfloat162 bf2;

// ---------------- helpers ----------------
__device__ __forceinline__ u64 ffma2(u64 a, u64 b, u64 c) {
    u64 d;
    asm("fma.rn.f32x2 %0, %1, %2, %3;" : "=l"(d) : "l"(a), "l"(b), "l"(c));
    return d;
}
__device__ __forceinline__ float2 u2f2(u64 u) {
    float2 f;
    asm("mov.b64 {%0, %1}, %2;" : "=f"(f.x), "=f"(f.y) : "l"(u));
    return f;
}
// 3-way bf16 split: x == h + m + l exactly (8+8+8 bits cover fp32's 24-bit mantissa)
__device__ __forceinline__ void split3(float x, __nv_bfloat16& h, __nv_bfloat16& m,
                                       __nv_bfloat16& l) {
    h = __float2bfloat16_rn(x);
    float r1 = x - __bfloat162float(h);
    m = __float2bfloat16_rn(r1);
    float r2 = r1 - __bfloat162float(m);
    l = __float2bfloat16_rn(r2);
}
// D += A(16x16) * B(16x8), bf16 in, f32 accum
__device__ __forceinline__ void mma_bf16(float* c, unsigned a0, unsigned a1,
                                         unsigned a2, unsigned a3,
                                         unsigned b0, unsigned b1) {
    asm("mma.sync.aligned.m16n8k16.row.col.f32.bf16.bf16.f32 "
        "{%0,%1,%2,%3}, {%4,%5,%6,%7}, {%8,%9}, {%0,%1,%2,%3};"
        : "+f"(c[0]), "+f"(c[1]), "+f"(c[2]), "+f"(c[3])
        : "r"(a0), "r"(a1), "r"(a2), "r"(a3), "r"(b0), "r"(b1));
}

// -------- scratch (device globals; no runtime allocation) --------
__device__ float g_x1[(size_t)BATCH*CMID*TLEN];
__device__ float g_x2[(size_t)BATCH*CMID*TLEN];
__device__ float g_z [(size_t)POSN*VQD];
#define WT2_WORDS ((size_t)(CMID/16)*5*8*CMID)
#define WT1_WORDS ((size_t)(CIN1/16)*5*8*CMID)
__device__ bf2 g_wt2h[WT2_WORDS]; __device__ bf2 g_wt2m[WT2_WORDS]; __device__ bf2 g_wt2l[WT2_WORDS];
__device__ bf2 g_wt1h[WT1_WORDS]; __device__ bf2 g_wt1m[WT1_WORDS]; __device__ bf2 g_wt1l[WT1_WORDS];

__global__ void nop_kernel() {}

// ============================================================================
// Weight transform: w (256, Cin, 5) -> [chunk][kw][ci2][co] {ci even, ci odd}
// ============================================================================
__global__ void wtrans_kernel(const float* __restrict__ w,
                              bf2* __restrict__ th, bf2* __restrict__ tm,
                              bf2* __restrict__ tl, int Cin)
{
    int idx = blockIdx.x * 256 + threadIdx.x;
    int total = (Cin/16) * 5 * 8 * 256;
    if (idx >= total) return;
    int co   = idx & 255;
    int rest = idx >> 8;
    int ci2  = rest & 7;
    int kw   = (rest >> 3) % 5;
    int chunk = rest / 40;
    int ci0 = chunk*16 + 2*ci2;
    float w0 = w[(size_t)co*Cin*5 + (size_t)ci0*5 + kw];
    float w1 = w[(size_t)co*Cin*5 + (size_t)(ci0+1)*5 + kw];
    __nv_bfloat16 h0,m0,l0,h1,m1,l1;
    split3(w0, h0, m0, l0);
    split3(w1, h1, m1, l1);
    th[idx] = __halves2bfloat162(h0, h1);
    tm[idx] = __halves2bfloat162(m0, m1);
    tl[idx] = __halves2bfloat162(l0, l1);
}

// ============================================================================
// Implicit-GEMM conv (k=5, pad=2, Cout=256) + BN + ReLU, bf16x6 split.
// R11's proven in-kernel-split staging; 6 mmas per k16 (mm,hl,lh,mh,hm,hh —
// dropped ml/lm ~2^-26, validated rel_err-neutral in R14). Short-chain temp-C
// + RN flush kills the tensor-core RZ-chain bias.
// block 256 (8 warps), tile M=64 co x N=64 t; warp m16 x n32.
// ============================================================================
#define XSS 72
#define WSS 72

__global__ __launch_bounds__(256, 2)
void convmma_kernel(const float* __restrict__ X,
                    const bf2* __restrict__ wth, const bf2* __restrict__ wtm,
                    const bf2* __restrict__ wtl,
                    float* __restrict__ Y, int Cin,
                    const float* __restrict__ cb_, const float* __restrict__ g_,
                    const float* __restrict__ be_, const float* __restrict__ m_,
                    const float* __restrict__ v_)
{
    __shared__ bf2 xsh[8*XSS], xsm[8*XSS], xsl[8*XSS];
    __shared__ bf2 wsh[40*WSS], wsm[40*WSS], wsl[40*WSS];

    const int t0   = blockIdx.x * 64;
    const int co0  = blockIdx.y * 64;
    const int b    = blockIdx.z;
    const int tid  = threadIdx.x;
    const int lane = tid & 31;
    const int wid  = tid >> 5;
    const int wm   = wid & 3;
    const int wn   = wid >> 2;
    const int qr   = lane >> 2;
    const int qc   = lane & 3;

    const float* Xb = X + (size_t)b * Cin * TLEN;

    float cm[4][4];
#pragma unroll
    for (int j = 0; j < 4; j++)
#pragma unroll
        for (int i = 0; i < 4; i++) cm[j][i] = 0.f;

    const unsigned* uxsh = (const unsigned*)xsh;
    const unsigned* uxsm = (const unsigned*)xsm;
    const unsigned* uxsl = (const unsigned*)xsl;
    const unsigned* uwsh = (const unsigned*)wsh;
    const unsigned* uwsm = (const unsigned*)wsm;
    const unsigned* uwsl = (const unsigned*)wsl;

    const int nchunk = Cin >> 4;
    for (int chunk = 0; chunk < nchunk; chunk++) {
        __syncthreads();
        for (int i = tid; i < 8*68; i += 256) {
            int ci2 = i / 68, j = i % 68;
            int t = t0 - 2 + j;
            float x0 = 0.f, x1 = 0.f;
            if (t >= 0 && t < TLEN) {
                const float* xp = Xb + (size_t)(chunk*16 + 2*ci2)*TLEN + t;
                x0 = xp[0];
                x1 = xp[TLEN];
            }
            __nv_bfloat16 h0,m0,l0,h1,m1,l1;
            split3(x0, h0, m0, l0);
            split3(x1, h1, m1, l1);
            xsh[ci2*XSS + i%68] = __halves2bfloat162(h0, h1);
            xsm[ci2*XSS + i%68] = __halves2bfloat162(m0, m1);
            xsl[ci2*XSS + i%68] = __halves2bfloat162(l0, l1);
        }
        {
            const size_t srcbase = (size_t)chunk * 40 * 256;
            for (int i = tid; i < 40*64; i += 256) {
                int r = i >> 6, m = i & 63;
                size_t s = srcbase + (size_t)r*256 + co0 + m;
                wsh[r*WSS + m] = wth[s];
                wsm[r*WSS + m] = wtm[s];
                wsl[r*WSS + m] = wtl[s];
            }
        }
        __syncthreads();

#pragma unroll
        for (int kw = 0; kw < 5; kw++) {
            const int ra = (kw*8 + qc)*WSS + wm*16 + qr;
            const int rb = (kw*8 + qc + 4)*WSS + wm*16 + qr;
            unsigned Ah0 = uwsh[ra], Ah1 = uwsh[ra+8], Ah2 = uwsh[rb], Ah3 = uwsh[rb+8];
            unsigned Am0 = uwsm[ra], Am1 = uwsm[ra+8], Am2 = uwsm[rb], Am3 = uwsm[rb+8];
            unsigned Al0 = uwsl[ra], Al1 = uwsl[ra+8], Al2 = uwsl[rb], Al3 = uwsl[rb+8];
#pragma unroll
            for (int j = 0; j < 4; j++) {
                const int toff = wn*32 + j*8 + qr + kw;
                const int x0i = qc*XSS + toff;
                const int x1i = (qc+4)*XSS + toff;
                unsigned Bh0 = uxsh[x0i], Bh1 = uxsh[x1i];
                unsigned Bm0 = uxsm[x0i], Bm1 = uxsm[x1i];
                unsigned Bl0 = uxsl[x0i], Bl1 = uxsl[x1i];
                // 6 terms ascending magnitude into zeroed temp; RN flush
                float ct[4] = {0.f, 0.f, 0.f, 0.f};
                mma_bf16(ct, Am0,Am1,Am2,Am3, Bm0,Bm1);   // m*m
                mma_bf16(ct, Ah0,Ah1,Ah2,Ah3, Bl0,Bl1);   // h*l
                mma_bf16(ct, Al0,Al1,Al2,Al3, Bh0,Bh1);   // l*h
                mma_bf16(ct, Am0,Am1,Am2,Am3, Bh0,Bh1);   // m*h
                mma_bf16(ct, Ah0,Ah1,Ah2,Ah3, Bm0,Bm1);   // h*m
                mma_bf16(ct, Ah0,Ah1,Ah2,Ah3, Bh0,Bh1);   // h*h
#pragma unroll
                for (int i = 0; i < 4; i++) cm[j][i] += ct[i];
            }
        }
    }

    const int r0 = co0 + wm*16 + qr;
    const int r1 = r0 + 8;
    float s0 = g_[r0] * rsqrtf(v_[r0] + 1e-5f);
    float s1 = g_[r1] * rsqrtf(v_[r1] + 1e-5f);
    float bb0 = (cb_[r0] - m_[r0]) * s0 + be_[r0];
    float bb1 = (cb_[r1] - m_[r1]) * s1 + be_[r1];
    float* Y0 = Y + (size_t)b*CMID*TLEN + (size_t)r0*TLEN;
    float* Y1 = Y + (size_t)b*CMID*TLEN + (size_t)r1*TLEN;
#pragma unroll
    for (int j = 0; j < 4; j++) {
        int cn = t0 + wn*32 + j*8 + 2*qc;
        float y00 = fmaf(cm[j][0], s0, bb0); y00 = y00 > 0.f ? y00 : 0.f;
        float y01 = fmaf(cm[j][1], s0, bb0); y01 = y01 > 0.f ? y01 : 0.f;
        float y10 = fmaf(cm[j][2], s1, bb1); y10 = y10 > 0.f ? y10 : 0.f;
        float y11 = fmaf(cm[j][3], s1, bb1); y11 = y11 > 0.f ? y11 : 0.f;
        *(float2*)(Y0 + cn) = make_float2(y00, y01);
        *(float2*)(Y1 + cn) = make_float2(y10, y11);
    }
}

// ============================================================================
// Kernel 3: downsample conv (256->128, k=24, stride=12, pad=6). exact fp32.
// k paired -> broadcast LDS.128 x-reads (halves x smem wavefronts).
// ============================================================================
#define DC 8
#define D_SMEM (DC*300*8 + DC*24*64*4)

__global__ __launch_bounds__(256, 3)
void down_kernel(const float* __restrict__ wd, const float* __restrict__ bd,
                 float* __restrict__ out)
{
    extern __shared__ float smd[];
    float2* xsd = (float2*)smd;
    float*  ws  = smd + DC*300*2;

    const int tp0 = blockIdx.x * 24;
    const int co0 = blockIdx.y * 64;
    const int b   = blockIdx.z;
    const int tid = threadIdx.x;
    const int cp  = tid & 31;
    const int tg  = tid >> 5;

    const float* xb = g_x2 + (size_t)b*CMID*TLEN;
    const int base = tp0*DSTR - 6;

    u64 acc[3] = {0ull, 0ull, 0ull};

    for (int c0 = 0; c0 < CMID; c0 += DC) {
        __syncthreads();
        for (int i = tid; i < DC*300; i += 256) {
            int ci = i / 300, j = i % 300;
            int t = base + j;
            float v = (t >= 0 && t < TLEN) ? xb[(size_t)(c0+ci)*TLEN + t] : 0.f;
            xsd[i] = make_float2(v, v);
        }
        for (int i = tid; i < DC*24*64; i += 256) {
            int co = i & 63, r = i >> 6;
            ws[i] = wd[(size_t)(co0+co)*(CMID*24) + c0*24 + r];
        }
        __syncthreads();

#pragma unroll 1
        for (int ci = 0; ci < DC; ci++) {
            const u64* xrow = (const u64*)(xsd + ci*300 + tg*36);
            const float* wrow = ws + ci*24*64 + 2*cp;
#pragma unroll 4
            for (int kk = 0; kk < 12; kk++) {
                const int k = 2*kk;
                u64 w0 = *(const u64*)(wrow + k*64);
                u64 w1 = *(const u64*)(wrow + (k+1)*64);
#pragma unroll
                for (int tt = 0; tt < 3; tt++) {
                    // aligned 16B broadcast: x[tt*12+k], x[tt*12+k+1]
                    ulonglong2 xp = *(const ulonglong2*)(xrow + tt*12 + k);
                    acc[tt] = ffma2(w0, xp.x, acc[tt]);
                    acc[tt] = ffma2(w1, xp.y, acc[tt]);
                }
            }
        }
    }

    const int co = co0 + 2*cp;
    const float b0 = bd[co], b1v = bd[co+1];
#pragma unroll
    for (int tt = 0; tt < 3; tt++) {
        int tp = tp0 + tg*3 + tt;
        if (tp < TP) {
            float2 v = u2f2(acc[tt]);
            out[(size_t)b*EMB*TP + (size_t)co*TP + tp]     = v.x + b0;
            out[(size_t)b*EMB*TP + (size_t)(co+1)*TP + tp] = v.y + b1v;
        }
    }
}

// ============================================================================
// Kernel 4: 1x1 projection e_a(128) -> z(16).
// ============================================================================
__global__ __launch_bounds__(256)
void proj_kernel(const float* __restrict__ out,
                 const float* __restrict__ wp, const float* __restrict__ bp)
{
    __shared__ float xs[EMB*64];
    __shared__ float wps[VQD*EMB];

    const int tp0 = blockIdx.x * 64;
    const int b   = blockIdx.y;
    const int tid = threadIdx.x;
    const int tp_l = tid & 63;
    const int dbase = tid >> 6;

    for (int i = tid; i < EMB*64; i += 256) {
        int e = i >> 6, tl = i & 63;
        int tp = tp0 + tl;
        xs[i] = (tp < TP) ? out[(size_t)b*EMB*TP + (size_t)e*TP + tp] : 0.f;
    }
    for (int i = tid; i < VQD*EMB; i += 256) wps[i] = wp[i];
    __syncthreads();

    float acc[4] = {0.f, 0.f, 0.f, 0.f};
    for (int e = 0; e < EMB; e++) {
        float xv = xs[e*64 + tp_l];
#pragma unroll
        for (int dd = 0; dd < 4; dd++)
            acc[dd] = fmaf(wps[(dd*4 + dbase)*EMB + e], xv, acc[dd]);
    }

    int tp = tp0 + tp_l;
    if (tp < TP) {
#pragma unroll
        for (int dd = 0; dd < 4; dd++) {
            int d = dd*4 + dbase;
            g_z[((size_t)b*TP + tp)*VQD + d] = acc[dd] + bp[d];
        }
    }
}

// ============================================================================
// Kernel 5: residual VQ, 8 stages.
// ============================================================================
__global__ __launch_bounds__(256)
void rvq_kernel(const float* __restrict__ codebooks, float* __restrict__ out)
{
    __shared__ float cbs[NCODE * VQD];
    __shared__ float cc[NCODE];

    const int tid = threadIdx.x;
    const int pos = blockIdx.x * 256 + tid;
    const bool valid = pos < POSN;

    float r[VQD];
    if (valid) {
#pragma unroll
        for (int d = 0; d < VQD; d++) r[d] = g_z[(size_t)pos*VQD + d];
    }

    for (int q = 0; q < NQ; q++) {
        __syncthreads();
        for (int i = tid; i < NCODE*VQD; i += 256)
            cbs[i] = codebooks[(size_t)q*NCODE*VQD + i];
        __syncthreads();
        {
            float s = 0.f;
#pragma unroll
            for (int d = 0; d < VQD; d++) {
                float c = cbs[tid*VQD + d];
                s = fmaf(c, c, s);
            }
            cc[tid] = s;
        }
        __syncthreads();

        if (valid) {
            int best = 0;
            float bestd = 3.4e38f;
            for (int code = 0; code < NCODE; code++) {
                float dot = 0.f;
#pragma unroll
                for (int d = 0; d < VQD; d++)
                    dot = fmaf(r[d], cbs[code*VQD + d], dot);
                float sc = cc[code] - 2.f*dot;
                if (sc < bestd) { bestd = sc; best = code; }
            }
            out[EA_SIZE + (size_t)q*POSN + pos] = (float)best;
#pragma unroll
            for (int d = 0; d < VQD; d++) r[d] -= cbs[best*VQD + d];
        }
    }
}

// ============================================================================
extern "C" void kernel_launch(void* const* d_in, const int* in_sizes, int n_in,
                              void* d_out, int out_size)
{
    const float* mel = (const float*)d_in[0];
    const float* w1  = (const float*)d_in[1];
    const float* b1  = (const float*)d_in[2];
    const float* g1  = (const float*)d_in[3];
    const float* be1 = (const float*)d_in[4];
    const float* m1  = (const float*)d_in[5];
    const float* v1  = (const float*)d_in[6];
    const float* w2  = (const float*)d_in[7];
    const float* b2  = (const float*)d_in[8];
    const float* g2  = (const float*)d_in[9];
    const float* be2 = (const float*)d_in[10];
    const float* m2  = (const float*)d_in[11];
    const float* v2  = (const float*)d_in[12];
    const float* wd  = (const float*)d_in[13];
    const float* bd  = (const float*)d_in[14];
    const float* wp  = (const float*)d_in[15];
    const float* bp  = (const float*)d_in[16];
    const float* cb  = (const float*)d_in[17];
    float* out = (float*)d_out;

    bf2 *w2h, *w2m, *w2l, *w1h, *w1m, *w1l;
    cudaGetSymbolAddress((void**)&w2h, g_wt2h);
    cudaGetSymbolAddress((void**)&w2m, g_wt2m);
    cudaGetSymbolAddress((void**)&w2l, g_wt2l);
    cudaGetSymbolAddress((void**)&w1h, g_wt1h);
    cudaGetSymbolAddress((void**)&w1m, g_wt1m);
    cudaGetSymbolAddress((void**)&w1l, g_wt1l);
    float *x1p, *x2p;
    cudaGetSymbolAddress((void**)&x1p, g_x1);
    cudaGetSymbolAddress((void**)&x2p, g_x2);

    cudaFuncSetAttribute(down_kernel, cudaFuncAttributeMaxDynamicSharedMemorySize, D_SMEM);

    // launch order puts down_kernel at index 5 (ncu -s 5 -c 1 capture slot)
    wtrans_kernel<<<((CMID/16)*5*8*256 + 255)/256, 256>>>(w2, w2h, w2m, w2l, CMID);   // 0
    wtrans_kernel<<<((CIN1/16)*5*8*256 + 255)/256, 256>>>(w1, w1h, w1m, w1l, CIN1);   // 1
    convmma_kernel<<<dim3(TLEN/64, CMID/64, BATCH), 256>>>(                            // 2
        mel, w1h, w1m, w1l, x1p, CIN1, b1, g1, be1, m1, v1);
    nop_kernel<<<1, 32>>>();                                                           // 3
    convmma_kernel<<<dim3(TLEN/64, CMID/64, BATCH), 256>>>(                            // 4
        x1p, w2h, w2m, w2l, x2p, CMID, b2, g2, be2, m2, v2);
    down_kernel<<<dim3((TP + 23)/24, EMB/64, BATCH), 256, D_SMEM>>>(wd, bd, out);      // 5
    proj_kernel<<<dim3((TP + 63)/64, BATCH), 256>>>(out, wp, bp);                      // 6
    rvq_kernel<<<(POSN + 255)/256, 256>>>(cb, out);                                    // 7
}

// round 16
// speedup vs baseline: 1.2701x; 1.0989x over previous
#include <cuda_runtime.h>
#include <cuda_bf16.h>
#include <cstdint>

#define BATCH 16
#define CIN1  80
#define CMID  256
#define TLEN  4096
#define EMB   128
#define DSTR  12
#define TP    341
#define VQD   16
#define NQ    8
#define NCODE 256

#define EA_SIZE (BATCH*EMB*TP)     // 698368
#define POSN    (BATCH*TP)         // 5456

typedef unsigned long long u64;
typedef __nv_bfloat162 bf2;

// ---------------- helpers ----------------
__device__ __forceinline__ u64 ffma2(u64 a, u64 b, u64 c) {
    u64 d;
    asm("fma.rn.f32x2 %0, %1, %2, %3;" : "=l"(d) : "l"(a), "l"(b), "l"(c));
    return d;
}
__device__ __forceinline__ float2 u2f2(u64 u) {
    float2 f;
    asm("mov.b64 {%0, %1}, %2;" : "=f"(f.x), "=f"(f.y) : "l"(u));
    return f;
}
__device__ __forceinline__ uint32_t smem_u32(const void* p) {
    uint32_t a;
    asm("{ .reg .u64 t; cvta.to.shared.u64 t, %1; cvt.u32.u64 %0, t; }" : "=r"(a) : "l"(p));
    return a;
}
// 3-way bf16 split: x == h + m + l exactly
__device__ __forceinline__ void split3(float x, __nv_bfloat16& h, __nv_bfloat16& m,
                                       __nv_bfloat16& l) {
    h = __float2bfloat16_rn(x);
    float r1 = x - __bfloat162float(h);
    m = __float2bfloat16_rn(r1);
    float r2 = r1 - __bfloat162float(m);
    l = __float2bfloat16_rn(r2);
}
__device__ __forceinline__ void mma_bf16(float* c, unsigned a0, unsigned a1,
                                         unsigned a2, unsigned a3,
                                         unsigned b0, unsigned b1) {
    asm("mma.sync.aligned.m16n8k16.row.col.f32.bf16.bf16.f32 "
        "{%0,%1,%2,%3}, {%4,%5,%6,%7}, {%8,%9}, {%0,%1,%2,%3};"
        : "+f"(c[0]), "+f"(c[1]), "+f"(c[2]), "+f"(c[3])
        : "r"(a0), "r"(a1), "r"(a2), "r"(a3), "r"(b0), "r"(b1));
}

// -------- scratch --------
__device__ float g_x1[(size_t)BATCH*CMID*TLEN];
__device__ float g_x2[(size_t)BATCH*CMID*TLEN];
__device__ float g_z [(size_t)POSN*VQD];
#define WT2_WORDS ((size_t)(CMID/16)*5*8*CMID)
#define WT1_WORDS ((size_t)(CIN1/16)*5*8*CMID)
__device__ bf2 g_wt2h[WT2_WORDS]; __device__ bf2 g_wt2m[WT2_WORDS]; __device__ bf2 g_wt2l[WT2_WORDS];
__device__ bf2 g_wt1h[WT1_WORDS]; __device__ bf2 g_wt1m[WT1_WORDS]; __device__ bf2 g_wt1l[WT1_WORDS];

// ============================================================================
// Weight transform (unchanged)
// ============================================================================
__global__ void wtrans_kernel(const float* __restrict__ w,
                              bf2* __restrict__ th, bf2* __restrict__ tm,
                              bf2* __restrict__ tl, int Cin)
{
    int idx = blockIdx.x * 256 + threadIdx.x;
    int total = (Cin/16) * 5 * 8 * 256;
    if (idx >= total) return;
    int co   = idx & 255;
    int rest = idx >> 8;
    int ci2  = rest & 7;
    int kw   = (rest >> 3) % 5;
    int chunk = rest / 40;
    int ci0 = chunk*16 + 2*ci2;
    float w0 = w[(size_t)co*Cin*5 + (size_t)ci0*5 + kw];
    float w1 = w[(size_t)co*Cin*5 + (size_t)(ci0+1)*5 + kw];
    __nv_bfloat16 h0,m0,l0,h1,m1,l1;
    split3(w0, h0, m0, l0);
    split3(w1, h1, m1, l1);
    th[idx] = __halves2bfloat162(h0, h1);
    tm[idx] = __halves2bfloat162(m0, m1);
    tl[idx] = __halves2bfloat162(l0, l1);
}

// ============================================================================
// Implicit-GEMM conv + BN + ReLU, bf16x6 (value-identical to R15 arithmetic),
// now double-buffered: cp.async w(k+1) + register-staged x(k+1) overlap mma(k).
// ============================================================================
#define XSS 72
#define WSS 72
#define XREG 576            // 8*72 words per x level
#define WREG 2880           // 40*72 words per w level
#define BUFW (3*XREG + 3*WREG)   // 10368 bf2 words per buffer
#define CONV_SMEM (2*BUFW*4)     // 82944 B

__global__ __launch_bounds__(256, 2)
void convmma_kernel(const float* __restrict__ X,
                    const bf2* __restrict__ wth, const bf2* __restrict__ wtm,
                    const bf2* __restrict__ wtl,
                    float* __restrict__ Y, int Cin,
                    const float* __restrict__ cb_, const float* __restrict__ g_,
                    const float* __restrict__ be_, const float* __restrict__ m_,
                    const float* __restrict__ v_)
{
    extern __shared__ bf2 smbuf[];

    const int t0   = blockIdx.x * 64;
    const int co0  = blockIdx.y * 64;
    const int b    = blockIdx.z;
    const int tid  = threadIdx.x;
    const int lane = tid & 31;
    const int wid  = tid >> 5;
    const int wm   = wid & 3;
    const int wn   = wid >> 2;
    const int qr   = lane >> 2;
    const int qc   = lane & 3;

    const float* Xb = X + (size_t)b * Cin * TLEN;
    const int nchunk = Cin >> 4;

    float cm[4][4];
#pragma unroll
    for (int j = 0; j < 4; j++)
#pragma unroll
        for (int i = 0; i < 4; i++) cm[j][i] = 0.f;

    float xa[3], xb_[3];

    // ---- staging lambdas (macros for clarity) ----
#define LDG_X(chunk_)                                                        \
    _Pragma("unroll")                                                        \
    for (int it = 0; it < 3; it++) {                                         \
        int i = tid + it*256;                                                \
        float x0 = 0.f, x1 = 0.f;                                            \
        if (i < 544) {                                                       \
            int ci2 = i / 68, j = i - ci2*68;                                \
            int t = t0 - 2 + j;                                              \
            if (t >= 0 && t < TLEN) {                                        \
                const float* xp = Xb + (size_t)((chunk_)*16 + 2*ci2)*TLEN + t;\
                x0 = xp[0]; x1 = xp[TLEN];                                   \
            }                                                                \
        }                                                                    \
        xa[it] = x0; xb_[it] = x1;                                           \
    }

#define STS_X(dstbuf)                                                        \
    _Pragma("unroll")                                                        \
    for (int it = 0; it < 3; it++) {                                         \
        int i = tid + it*256;                                                \
        if (i < 544) {                                                       \
            int ci2 = i / 68, j = i - ci2*68;                                \
            __nv_bfloat16 h0,m0,l0,h1,m1,l1;                                 \
            split3(xa[it], h0, m0, l0);                                      \
            split3(xb_[it], h1, m1, l1);                                     \
            (dstbuf)[ci2*XSS + j]          = __halves2bfloat162(h0, h1);     \
            (dstbuf)[XREG + ci2*XSS + j]   = __halves2bfloat162(m0, m1);     \
            (dstbuf)[2*XREG + ci2*XSS + j] = __halves2bfloat162(l0, l1);     \
        }                                                                    \
    }

#define CPA_W(dstbuf, chunk_)                                                \
    {                                                                        \
        const size_t srcbase = (size_t)(chunk_) * 40 * 256 + co0;            \
        _Pragma("unroll")                                                    \
        for (int it = 0; it < 8; it++) {                                     \
            int i = tid + it*256;                                            \
            if (i < 1920) {                                                  \
                int lev = i / 640;                                           \
                int rem = i - lev*640;                                       \
                int r = rem >> 4, q = (rem & 15) << 2;                       \
                const bf2* src = (lev == 0 ? wth : (lev == 1 ? wtm : wtl))   \
                                 + srcbase + (size_t)r*256 + q;              \
                uint32_t da = smem_u32((dstbuf) + 3*XREG + lev*WREG + r*WSS + q); \
                asm volatile("cp.async.cg.shared.global [%0], [%1], 16;"     \
                             :: "r"(da), "l"(src));                          \
            }                                                                \
        }                                                                    \
        asm volatile("cp.async.commit_group;");                              \
    }

    // ---- prologue: stage chunk 0 ----
    LDG_X(0);
    STS_X(smbuf);
    CPA_W(smbuf, 0);

    for (int chunk = 0; chunk < nchunk; chunk++) {
        bf2* buf  = smbuf + (chunk & 1) * BUFW;
        bf2* nbuf = smbuf + ((chunk & 1) ^ 1) * BUFW;

        asm volatile("cp.async.wait_group 0;" ::: "memory");
        __syncthreads();

        const bool has = (chunk + 1) < nchunk;
        if (has) {
            LDG_X(chunk + 1);          // LDG issued; data consumed after mma
            CPA_W(nbuf, chunk + 1);    // async, waits at next iteration
        }

        const unsigned* uxsh = (const unsigned*)buf;
        const unsigned* uxsm = (const unsigned*)(buf + XREG);
        const unsigned* uxsl = (const unsigned*)(buf + 2*XREG);
        const unsigned* uwsh = (const unsigned*)(buf + 3*XREG);
        const unsigned* uwsm = (const unsigned*)(buf + 3*XREG + WREG);
        const unsigned* uwsl = (const unsigned*)(buf + 3*XREG + 2*WREG);

#pragma unroll
        for (int kw = 0; kw < 5; kw++) {
            const int ra = (kw*8 + qc)*WSS + wm*16 + qr;
            const int rb = (kw*8 + qc + 4)*WSS + wm*16 + qr;
            unsigned Ah0 = uwsh[ra], Ah1 = uwsh[ra+8], Ah2 = uwsh[rb], Ah3 = uwsh[rb+8];
            unsigned Am0 = uwsm[ra], Am1 = uwsm[ra+8], Am2 = uwsm[rb], Am3 = uwsm[rb+8];
            unsigned Al0 = uwsl[ra], Al1 = uwsl[ra+8], Al2 = uwsl[rb], Al3 = uwsl[rb+8];
#pragma unroll
            for (int j = 0; j < 4; j++) {
                const int toff = wn*32 + j*8 + qr + kw;
                const int x0i = qc*XSS + toff;
                const int x1i = (qc+4)*XSS + toff;
                unsigned Bh0 = uxsh[x0i], Bh1 = uxsh[x1i];
                unsigned Bm0 = uxsm[x0i], Bm1 = uxsm[x1i];
                unsigned Bl0 = uxsl[x0i], Bl1 = uxsl[x1i];
                float ct[4] = {0.f, 0.f, 0.f, 0.f};
                mma_bf16(ct, Am0,Am1,Am2,Am3, Bm0,Bm1);   // m*m
                mma_bf16(ct, Ah0,Ah1,Ah2,Ah3, Bl0,Bl1);   // h*l
                mma_bf16(ct, Al0,Al1,Al2,Al3, Bh0,Bh1);   // l*h
                mma_bf16(ct, Am0,Am1,Am2,Am3, Bh0,Bh1);   // m*h
                mma_bf16(ct, Ah0,Ah1,Ah2,Ah3, Bm0,Bm1);   // h*m
                mma_bf16(ct, Ah0,Ah1,Ah2,Ah3, Bh0,Bh1);   // h*h
#pragma unroll
                for (int i = 0; i < 4; i++) cm[j][i] += ct[i];
            }
        }

        if (has) { STS_X(nbuf); }      // after mma(k): hazard-free vs mma(k-1)
    }

    const int r0 = co0 + wm*16 + qr;
    const int r1 = r0 + 8;
    float s0 = g_[r0] * rsqrtf(v_[r0] + 1e-5f);
    float s1 = g_[r1] * rsqrtf(v_[r1] + 1e-5f);
    float bb0 = (cb_[r0] - m_[r0]) * s0 + be_[r0];
    float bb1 = (cb_[r1] - m_[r1]) * s1 + be_[r1];
    float* Y0 = Y + (size_t)b*CMID*TLEN + (size_t)r0*TLEN;
    float* Y1 = Y + (size_t)b*CMID*TLEN + (size_t)r1*TLEN;
#pragma unroll
    for (int j = 0; j < 4; j++) {
        int cn = t0 + wn*32 + j*8 + 2*qc;
        float y00 = fmaf(cm[j][0], s0, bb0); y00 = y00 > 0.f ? y00 : 0.f;
        float y01 = fmaf(cm[j][1], s0, bb0); y01 = y01 > 0.f ? y01 : 0.f;
        float y10 = fmaf(cm[j][2], s1, bb1); y10 = y10 > 0.f ? y10 : 0.f;
        float y11 = fmaf(cm[j][3], s1, bb1); y11 = y11 > 0.f ? y11 : 0.f;
        *(float2*)(Y0 + cn) = make_float2(y00, y01);
        *(float2*)(Y1 + cn) = make_float2(y10, y11);
    }
#undef LDG_X
#undef STS_X
#undef CPA_W
}

// ============================================================================
// Kernel 3: downsample conv — unchanged from R15 (LDS.128-paired).
// ============================================================================
#define DC 8
#define D_SMEM (DC*300*8 + DC*24*64*4)

__global__ __launch_bounds__(256, 3)
void down_kernel(const float* __restrict__ wd, const float* __restrict__ bd,
                 float* __restrict__ out)
{
    extern __shared__ float smd[];
    float2* xsd = (float2*)smd;
    float*  ws  = smd + DC*300*2;

    const int tp0 = blockIdx.x * 24;
    const int co0 = blockIdx.y * 64;
    const int b   = blockIdx.z;
    const int tid = threadIdx.x;
    const int cp  = tid & 31;
    const int tg  = tid >> 5;

    const float* xb = g_x2 + (size_t)b*CMID*TLEN;
    const int base = tp0*DSTR - 6;

    u64 acc[3] = {0ull, 0ull, 0ull};

    for (int c0 = 0; c0 < CMID; c0 += DC) {
        __syncthreads();
        for (int i = tid; i < DC*300; i += 256) {
            int ci = i / 300, j = i % 300;
            int t = base + j;
            float v = (t >= 0 && t < TLEN) ? xb[(size_t)(c0+ci)*TLEN + t] : 0.f;
            xsd[i] = make_float2(v, v);
        }
        for (int i = tid; i < DC*24*64; i += 256) {
            int co = i & 63, r = i >> 6;
            ws[i] = wd[(size_t)(co0+co)*(CMID*24) + c0*24 + r];
        }
        __syncthreads();

#pragma unroll 1
        for (int ci = 0; ci < DC; ci++) {
            const u64* xrow = (const u64*)(xsd + ci*300 + tg*36);
            const float* wrow = ws + ci*24*64 + 2*cp;
#pragma unroll 4
            for (int kk = 0; kk < 12; kk++) {
                const int k = 2*kk;
                u64 w0 = *(const u64*)(wrow + k*64);
                u64 w1 = *(const u64*)(wrow + (k+1)*64);
#pragma unroll
                for (int tt = 0; tt < 3; tt++) {
                    ulonglong2 xp = *(const ulonglong2*)(xrow + tt*12 + k);
                    acc[tt] = ffma2(w0, xp.x, acc[tt]);
                    acc[tt] = ffma2(w1, xp.y, acc[tt]);
                }
            }
        }
    }

    const int co = co0 + 2*cp;
    const float b0 = bd[co], b1v = bd[co+1];
#pragma unroll
    for (int tt = 0; tt < 3; tt++) {
        int tp = tp0 + tg*3 + tt;
        if (tp < TP) {
            float2 v = u2f2(acc[tt]);
            out[(size_t)b*EMB*TP + (size_t)co*TP + tp]     = v.x + b0;
            out[(size_t)b*EMB*TP + (size_t)(co+1)*TP + tp] = v.y + b1v;
        }
    }
}

// ============================================================================
// Kernel 4: 1x1 projection (unchanged).
// ============================================================================
__global__ __launch_bounds__(256)
void proj_kernel(const float* __restrict__ out,
                 const float* __restrict__ wp, const float* __restrict__ bp)
{
    __shared__ float xs[EMB*64];
    __shared__ float wps[VQD*EMB];

    const int tp0 = blockIdx.x * 64;
    const int b   = blockIdx.y;
    const int tid = threadIdx.x;
    const int tp_l = tid & 63;
    const int dbase = tid >> 6;

    for (int i = tid; i < EMB*64; i += 256) {
        int e = i >> 6, tl = i & 63;
        int tp = tp0 + tl;
        xs[i] = (tp < TP) ? out[(size_t)b*EMB*TP + (size_t)e*TP + tp] : 0.f;
    }
    for (int i = tid; i < VQD*EMB; i += 256) wps[i] = wp[i];
    __syncthreads();

    float acc[4] = {0.f, 0.f, 0.f, 0.f};
    for (int e = 0; e < EMB; e++) {
        float xv = xs[e*64 + tp_l];
#pragma unroll
        for (int dd = 0; dd < 4; dd++)
            acc[dd] = fmaf(wps[(dd*4 + dbase)*EMB + e], xv, acc[dd]);
    }

    int tp = tp0 + tp_l;
    if (tp < TP) {
#pragma unroll
        for (int dd = 0; dd < 4; dd++) {
            int d = dd*4 + dbase;
            g_z[((size_t)b*TP + tp)*VQD + d] = acc[dd] + bp[d];
        }
    }
}

// ============================================================================
// Kernel 5: residual VQ (unchanged).
// ============================================================================
__global__ __launch_bounds__(256)
void rvq_kernel(const float* __restrict__ codebooks, float* __restrict__ out)
{
    __shared__ float cbs[NCODE * VQD];
    __shared__ float cc[NCODE];

    const int tid = threadIdx.x;
    const int pos = blockIdx.x * 256 + tid;
    const bool valid = pos < POSN;

    float r[VQD];
    if (valid) {
#pragma unroll
        for (int d = 0; d < VQD; d++) r[d] = g_z[(size_t)pos*VQD + d];
    }

    for (int q = 0; q < NQ; q++) {
        __syncthreads();
        for (int i = tid; i < NCODE*VQD; i += 256)
            cbs[i] = codebooks[(size_t)q*NCODE*VQD + i];
        __syncthreads();
        {
            float s = 0.f;
#pragma unroll
            for (int d = 0; d < VQD; d++) {
                float c = cbs[tid*VQD + d];
                s = fmaf(c, c, s);
            }
            cc[tid] = s;
        }
        __syncthreads();

        if (valid) {
            int best = 0;
            float bestd = 3.4e38f;
            for (int code = 0; code < NCODE; code++) {
                float dot = 0.f;
#pragma unroll
                for (int d = 0; d < VQD; d++)
                    dot = fmaf(r[d], cbs[code*VQD + d], dot);
                float sc = cc[code] - 2.f*dot;
                if (sc < bestd) { bestd = sc; best = code; }
            }
            out[EA_SIZE + (size_t)q*POSN + pos] = (float)best;
#pragma unroll
            for (int d = 0; d < VQD; d++) r[d] -= cbs[best*VQD + d];
        }
    }
}

// ============================================================================
extern "C" void kernel_launch(void* const* d_in, const int* in_sizes, int n_in,
                              void* d_out, int out_size)
{
    const float* mel = (const float*)d_in[0];
    const float* w1  = (const float*)d_in[1];
    const float* b1  = (const float*)d_in[2];
    const float* g1  = (const float*)d_in[3];
    const float* be1 = (const float*)d_in[4];
    const float* m1  = (const float*)d_in[5];
    const float* v1  = (const float*)d_in[6];
    const float* w2  = (const float*)d_in[7];
    const float* b2  = (const float*)d_in[8];
    const float* g2  = (const float*)d_in[9];
    const float* be2 = (const float*)d_in[10];
    const float* m2  = (const float*)d_in[11];
    const float* v2  = (const float*)d_in[12];
    const float* wd  = (const float*)d_in[13];
    const float* bd  = (const float*)d_in[14];
    const float* wp  = (const float*)d_in[15];
    const float* bp  = (const float*)d_in[16];
    const float* cb  = (const float*)d_in[17];
    float* out = (float*)d_out;

    bf2 *w2h, *w2m, *w2l, *w1h, *w1m, *w1l;
    cudaGetSymbolAddress((void**)&w2h, g_wt2h);
    cudaGetSymbolAddress((void**)&w2m, g_wt2m);
    cudaGetSymbolAddress((void**)&w2l, g_wt2l);
    cudaGetSymbolAddress((void**)&w1h, g_wt1h);
    cudaGetSymbolAddress((void**)&w1m, g_wt1m);
    cudaGetSymbolAddress((void**)&w1l, g_wt1l);
    float *x1p, *x2p;
    cudaGetSymbolAddress((void**)&x1p, g_x1);
    cudaGetSymbolAddress((void**)&x2p, g_x2);

    cudaFuncSetAttribute(convmma_kernel, cudaFuncAttributeMaxDynamicSharedMemorySize, CONV_SMEM);
    cudaFuncSetAttribute(down_kernel,    cudaFuncAttributeMaxDynamicSharedMemorySize, D_SMEM);

    wtrans_kernel<<<((CMID/16)*5*8*256 + 255)/256, 256>>>(w2, w2h, w2m, w2l, CMID);   // 0
    wtrans_kernel<<<((CIN1/16)*5*8*256 + 255)/256, 256>>>(w1, w1h, w1m, w1l, CIN1);   // 1
    convmma_kernel<<<dim3(TLEN/64, CMID/64, BATCH), 256, CONV_SMEM>>>(                 // 2
        mel, w1h, w1m, w1l, x1p, CIN1, b1, g1, be1, m1, v1);
    convmma_kernel<<<dim3(TLEN/64, CMID/64, BATCH), 256, CONV_SMEM>>>(                 // 3
        x1p, w2h, w2m, w2l, x2p, CMID, b2, g2, be2, m2, v2);
    down_kernel<<<dim3((TP + 23)/24, EMB/64, BATCH), 256, D_SMEM>>>(wd, bd, out);      // 4
    proj_kernel<<<dim3((TP + 63)/64, BATCH), 256>>>(out, wp, bp);                      // 5
    rvq_kernel<<<(POSN + 255)/256, 256>>>(cb, out);                                    // 6
}